// round 2
// baseline (speedup 1.0000x reference)
#include <cuda_runtime.h>
#include <cuda_bf16.h>
#include <cstdint>

// Problem constants
#define NTOK 4096      // B*S = 2*2048
#define DM   1024      // d_model
#define NE   8         // experts
#define CAP  1024      // capacity = NTOK*2/8
#define HID  2816      // hidden
#define TOPK 2

// ---------------------------------------------------------------------------
// Static device scratch (no allocations allowed)
// ---------------------------------------------------------------------------
__device__ float g_xb[(size_t)NE * CAP * DM];     // gathered expert inputs (32 MB)
__device__ float g_h [(size_t)NE * CAP * HID];    // h1 then h = silu(h1)*h3 (92 MB)
__device__ int   g_slot_tok[NE * CAP];
__device__ float g_slot_gate[NE * CAP];
__device__ int   g_topi[NTOK * 2];
__device__ float g_gate[NTOK * 2];

// ---------------------------------------------------------------------------
// Kernel 1: router — logits, noisy logits, top-2, softmax gates
// one block (256 thr = 8 warps) per token; warp e handles expert e
// ---------------------------------------------------------------------------
__global__ __launch_bounds__(256) void router_kernel(
    const float* __restrict__ x, const float* __restrict__ noise,
    const float* __restrict__ rw, const float* __restrict__ rb,
    const float* __restrict__ nw, const float* __restrict__ nb)
{
    int t = blockIdx.x;
    __shared__ float xs[DM];
    __shared__ float sl[NE], sn[NE];

    const float4* xr = (const float4*)(x + (size_t)t * DM);
    for (int i = threadIdx.x; i < DM / 4; i += blockDim.x)
        ((float4*)xs)[i] = xr[i];
    __syncthreads();

    int w = threadIdx.x >> 5, lane = threadIdx.x & 31;
    const float* rwr = rw + w * DM;
    const float* nwr = nw + w * DM;
    float a = 0.f, b = 0.f;
    for (int k = lane; k < DM; k += 32) {
        float xv = xs[k];
        a = fmaf(rwr[k], xv, a);
        b = fmaf(nwr[k], xv, b);
    }
    #pragma unroll
    for (int o = 16; o; o >>= 1) {
        a += __shfl_down_sync(0xFFFFFFFFu, a, o);
        b += __shfl_down_sync(0xFFFFFFFFu, b, o);
    }
    if (lane == 0) { sl[w] = a + rb[w]; sn[w] = b + nb[w]; }
    __syncthreads();

    if (threadIdx.x == 0) {
        float nz[NE];
        #pragma unroll
        for (int e = 0; e < NE; e++) {
            float z  = sn[e];
            float sp = fmaxf(z, 0.f) + log1pf(expf(-fabsf(z)));   // stable softplus
            nz[e] = sl[e] + noise[t * NE + e] * sp;
        }
        int i0 = 0;
        #pragma unroll
        for (int e = 1; e < NE; e++) if (nz[e] > nz[i0]) i0 = e;
        int i1 = -1;
        #pragma unroll
        for (int e = 0; e < NE; e++) {
            if (e == i0) continue;
            if (i1 < 0 || nz[e] > nz[i1]) i1 = e;
        }
        float g0 = 1.f / (1.f + expf(nz[i1] - nz[i0]));  // softmax over top-2 (stable: arg<=0)
        g_topi[t * 2 + 0] = i0;
        g_topi[t * 2 + 1] = i1;
        g_gate[t * 2 + 0] = g0;
        g_gate[t * 2 + 1] = 1.f - g0;
    }
}

// ---------------------------------------------------------------------------
// Kernel 2: ordered capacity assignment — one block per expert, block scan
// ---------------------------------------------------------------------------
__global__ __launch_bounds__(256) void assign_kernel()
{
    int e = blockIdx.x;
    for (int c = threadIdx.x; c < CAP; c += blockDim.x) {
        g_slot_tok[e * CAP + c]  = NTOK;
        g_slot_gate[e * CAP + c] = 0.f;
    }
    __shared__ int base;
    __shared__ int warp_sums[8];
    if (threadIdx.x == 0) base = 0;
    __syncthreads();

    int lane = threadIdx.x & 31, w = threadIdx.x >> 5;
    for (int t0 = 0; t0 < NTOK; t0 += blockDim.x) {
        int t = t0 + threadIdx.x;
        int hit = 0; float g = 0.f;
        int i0 = g_topi[t * 2], i1 = g_topi[t * 2 + 1];
        if (i0 == e)       { hit = 1; g = g_gate[t * 2]; }
        else if (i1 == e)  { hit = 1; g = g_gate[t * 2 + 1]; }

        unsigned ball = __ballot_sync(0xFFFFFFFFu, hit);
        int wexc = __popc(ball & ((1u << lane) - 1u));
        if (lane == 0) warp_sums[w] = __popc(ball);
        __syncthreads();
        int woff = 0;
        for (int i = 0; i < w; i++) woff += warp_sums[i];
        int pos = base + woff + wexc;
        if (hit && pos < CAP) {
            g_slot_tok[e * CAP + pos]  = t;
            g_slot_gate[e * CAP + pos] = g;
        }
        __syncthreads();
        if (threadIdx.x == 0) {
            int tot = 0;
            for (int i = 0; i < 8; i++) tot += warp_sums[i];
            base += tot;
        }
        __syncthreads();
    }
}

// ---------------------------------------------------------------------------
// Kernel 3: gather tokens into per-expert buffers (zeros for empty slots)
// ---------------------------------------------------------------------------
__global__ __launch_bounds__(256) void gather_kernel(const float* __restrict__ x)
{
    int c = blockIdx.x, e = blockIdx.y;
    int tok = g_slot_tok[e * CAP + c];
    float4* dst = (float4*)(g_xb + ((size_t)e * CAP + c) * DM);
    if (tok < NTOK) {
        const float4* src = (const float4*)(x + (size_t)tok * DM);
        for (int i = threadIdx.x; i < DM / 4; i += blockDim.x) dst[i] = src[i];
    } else {
        float4 z = make_float4(0.f, 0.f, 0.f, 0.f);
        for (int i = threadIdx.x; i < DM / 4; i += blockDim.x) dst[i] = z;
    }
}

// ---------------------------------------------------------------------------
// zero output
// ---------------------------------------------------------------------------
__global__ void zero_kernel(float* __restrict__ out, int n4)
{
    float4 z = make_float4(0.f, 0.f, 0.f, 0.f);
    for (int i = blockIdx.x * blockDim.x + threadIdx.x; i < n4; i += gridDim.x * blockDim.x)
        ((float4*)out)[i] = z;
}

// ---------------------------------------------------------------------------
// GEMM: C[m][n] = sum_k A[m][k]*B[n][k]   (both row-major, K contiguous)
// Block tile 128x128, K-tile 16, 256 threads, 8x8 per thread, double-buffered.
// MODE 0: C = acc                       (h1 = xb @ w1^T)
// MODE 1: C = silu(C) * acc             (h  = silu(h1) * (xb @ w3^T)), in-place on g_h
// MODE 2: atomic scatter to out with gate (o = h @ w2^T)
// ---------------------------------------------------------------------------
template<int MODE>
__global__ __launch_bounds__(256, 2) void gemm_kernel(
    const float* __restrict__ Abase, const float* __restrict__ Bbase,
    float* __restrict__ Cbase, int M, int Nn, int K,
    float* __restrict__ out)
{
    const int e  = blockIdx.z;
    const float* A = Abase + (size_t)e * M * K;
    const float* B = Bbase + (size_t)e * Nn * K;
    float*       C = Cbase ? (Cbase + (size_t)e * M * Nn) : nullptr;

    const int bm = blockIdx.y * 128;
    const int bn = blockIdx.x * 128;

    __shared__ float As[2][16][128];
    __shared__ float Bs[2][16][128];

    const int tid  = threadIdx.x;
    const int lane = tid & 31;
    const int wid  = tid >> 5;
    const int wm   = wid & 1;        // 2 warp rows (64 each)
    const int wn   = wid >> 1;       // 4 warp cols (32 each)
    const int r0   = wm * 64 + (lane >> 2) * 8;
    const int c0   = wn * 32 + (lane & 3) * 8;

    // loader: each thread loads one 8-float half-row of each tile
    const int lrow = tid >> 1;             // 0..127
    const int lch  = (tid & 1) * 8;        // 0 or 8
    const float* Aptr = A + (size_t)(bm + lrow) * K + lch;
    const float* Bptr = B + (size_t)(bn + lrow) * K + lch;

    float acc[8][8];
    #pragma unroll
    for (int i = 0; i < 8; i++)
        #pragma unroll
        for (int j = 0; j < 8; j++) acc[i][j] = 0.f;

    float4 pa0, pa1, pb0, pb1;
    pa0 = *(const float4*)(Aptr);     pa1 = *(const float4*)(Aptr + 4);
    pb0 = *(const float4*)(Bptr);     pb1 = *(const float4*)(Bptr + 4);

    int buf = 0;
    {
        As[0][lch + 0][lrow] = pa0.x; As[0][lch + 1][lrow] = pa0.y;
        As[0][lch + 2][lrow] = pa0.z; As[0][lch + 3][lrow] = pa0.w;
        As[0][lch + 4][lrow] = pa1.x; As[0][lch + 5][lrow] = pa1.y;
        As[0][lch + 6][lrow] = pa1.z; As[0][lch + 7][lrow] = pa1.w;
        Bs[0][lch + 0][lrow] = pb0.x; Bs[0][lch + 1][lrow] = pb0.y;
        Bs[0][lch + 2][lrow] = pb0.z; Bs[0][lch + 3][lrow] = pb0.w;
        Bs[0][lch + 4][lrow] = pb1.x; Bs[0][lch + 5][lrow] = pb1.y;
        Bs[0][lch + 6][lrow] = pb1.z; Bs[0][lch + 7][lrow] = pb1.w;
    }
    __syncthreads();

    for (int kt = 16;; kt += 16) {
        const bool more = kt < K;
        if (more) {
            pa0 = *(const float4*)(Aptr + kt);  pa1 = *(const float4*)(Aptr + kt + 4);
            pb0 = *(const float4*)(Bptr + kt);  pb1 = *(const float4*)(Bptr + kt + 4);
        }
        #pragma unroll
        for (int kk = 0; kk < 16; kk++) {
            float a[8], b[8];
            *(float4*)&a[0] = *(const float4*)&As[buf][kk][r0];
            *(float4*)&a[4] = *(const float4*)&As[buf][kk][r0 + 4];
            *(float4*)&b[0] = *(const float4*)&Bs[buf][kk][c0];
            *(float4*)&b[4] = *(const float4*)&Bs[buf][kk][c0 + 4];
            #pragma unroll
            for (int i = 0; i < 8; i++)
                #pragma unroll
                for (int j = 0; j < 8; j++)
                    acc[i][j] = fmaf(a[i], b[j], acc[i][j]);
        }
        if (!more) break;
        buf ^= 1;
        As[buf][lch + 0][lrow] = pa0.x; As[buf][lch + 1][lrow] = pa0.y;
        As[buf][lch + 2][lrow] = pa0.z; As[buf][lch + 3][lrow] = pa0.w;
        As[buf][lch + 4][lrow] = pa1.x; As[buf][lch + 5][lrow] = pa1.y;
        As[buf][lch + 6][lrow] = pa1.z; As[buf][lch + 7][lrow] = pa1.w;
        Bs[buf][lch + 0][lrow] = pb0.x; Bs[buf][lch + 1][lrow] = pb0.y;
        Bs[buf][lch + 2][lrow] = pb0.z; Bs[buf][lch + 3][lrow] = pb0.w;
        Bs[buf][lch + 4][lrow] = pb1.x; Bs[buf][lch + 5][lrow] = pb1.y;
        Bs[buf][lch + 6][lrow] = pb1.z; Bs[buf][lch + 7][lrow] = pb1.w;
        __syncthreads();
    }

    // epilogue
    if (MODE == 0) {
        #pragma unroll
        for (int i = 0; i < 8; i++) {
            float* Crow = C + (size_t)(bm + r0 + i) * Nn + bn + c0;
            *(float4*)&Crow[0] = make_float4(acc[i][0], acc[i][1], acc[i][2], acc[i][3]);
            *(float4*)&Crow[4] = make_float4(acc[i][4], acc[i][5], acc[i][6], acc[i][7]);
        }
    } else if (MODE == 1) {
        #pragma unroll
        for (int i = 0; i < 8; i++) {
            float* Crow = C + (size_t)(bm + r0 + i) * Nn + bn + c0;
            float4 h0 = *(const float4*)&Crow[0];
            float4 h1 = *(const float4*)&Crow[4];
            float hv[8] = { h0.x, h0.y, h0.z, h0.w, h1.x, h1.y, h1.z, h1.w };
            float ov[8];
            #pragma unroll
            for (int j = 0; j < 8; j++) {
                float z = hv[j];
                float s = z / (1.f + expf(-z));   // silu
                ov[j] = s * acc[i][j];
            }
            *(float4*)&Crow[0] = make_float4(ov[0], ov[1], ov[2], ov[3]);
            *(float4*)&Crow[4] = make_float4(ov[4], ov[5], ov[6], ov[7]);
        }
    } else { // MODE 2: gated scatter-add into output
        #pragma unroll
        for (int i = 0; i < 8; i++) {
            int m   = bm + r0 + i;
            int tok = g_slot_tok[e * CAP + m];
            if (tok < NTOK) {
                float g = g_slot_gate[e * CAP + m];
                float* orow = out + (size_t)tok * DM + bn + c0;
                #pragma unroll
                for (int j = 0; j < 8; j++)
                    atomicAdd(orow + j, acc[i][j] * g);
            }
        }
    }
}

// ---------------------------------------------------------------------------
// Launch
// ---------------------------------------------------------------------------
extern "C" void kernel_launch(void* const* d_in, const int* in_sizes, int n_in,
                              void* d_out, int out_size)
{
    const float* x   = (const float*)d_in[0];   // (2,2048,1024)
    const float* nz  = (const float*)d_in[1];   // (2,2048,8)
    const float* rw  = (const float*)d_in[2];   // (8,1024)
    const float* rb  = (const float*)d_in[3];   // (8,)
    const float* nw  = (const float*)d_in[4];   // (8,1024)
    const float* nb  = (const float*)d_in[5];   // (8,)
    const float* w1  = (const float*)d_in[6];   // (8,2816,1024)
    const float* w3  = (const float*)d_in[7];   // (8,2816,1024)
    const float* w2  = (const float*)d_in[8];   // (8,1024,2816)
    float*       out = (float*)d_out;           // (2,2048,1024)

    float* xb = nullptr; float* h = nullptr;
    cudaGetSymbolAddress((void**)&xb, g_xb);
    cudaGetSymbolAddress((void**)&h,  g_h);

    // 1. routing
    router_kernel<<<NTOK, 256>>>(x, nz, rw, rb, nw, nb);
    // 2. ordered capacity assignment
    assign_kernel<<<NE, 256>>>();
    // 3. gather
    gather_kernel<<<dim3(CAP, NE), 256>>>(x);
    // 4. h1 = xb @ w1^T
    gemm_kernel<0><<<dim3(HID / 128, CAP / 128, NE), 256>>>(
        xb, w1, h, CAP, HID, DM, nullptr);
    // 5. h = silu(h1) * (xb @ w3^T)
    gemm_kernel<1><<<dim3(HID / 128, CAP / 128, NE), 256>>>(
        xb, w3, h, CAP, HID, DM, nullptr);
    // 6. zero output
    zero_kernel<<<512, 256>>>(out, NTOK * DM / 4);
    // 7. o = h @ w2^T, gated scatter-add
    gemm_kernel<2><<<dim3(DM / 128, CAP / 128, NE), 256>>>(
        h, w2, nullptr, CAP, DM, HID, out);
}

// round 9
// speedup vs baseline: 2.0609x; 2.0609x over previous
#include <cuda_runtime.h>
#include <cuda_bf16.h>
#include <cstdint>

#define NTOK 4096
#define DM   1024
#define NE   8
#define CAP  1024
#define HID  2816

// ---------------------------------------------------------------------------
// Static scratch
// ---------------------------------------------------------------------------
__device__ float         g_xb[(size_t)NE*CAP*DM];     // gathered inputs (fp32)
__device__ __nv_bfloat16 g_hh[(size_t)NE*CAP*HID];    // h hi (bf16)
__device__ __nv_bfloat16 g_hl[(size_t)NE*CAP*HID];    // h lo (bf16)
__device__ float         g_ob[(size_t)NE*CAP*DM];     // gated expert outputs
__device__ int   g_slot_tok[NE*CAP];
__device__ float g_slot_gate[NE*CAP];
__device__ int   g_topi[NTOK*2];
__device__ float g_gate[NTOK*2];
__device__ int   g_tok_slot[NTOK*2];                  // token -> expert slot (or -1)

// ---------------------------------------------------------------------------
// Helpers
// ---------------------------------------------------------------------------
__device__ __forceinline__ uint32_t smem_u32(const void* p){
    uint32_t a;
    asm("{ .reg .u64 t; cvta.to.shared.u64 t, %1; cvt.u32.u64 %0, t; }" : "=r"(a) : "l"(p));
    return a;
}
__device__ __forceinline__ uint32_t sw128(uint32_t b){ return b ^ ((b >> 3) & 0x70); }

__device__ __forceinline__ void ldsm4(uint32_t& r0, uint32_t& r1, uint32_t& r2, uint32_t& r3,
                                      uint32_t addr){
    asm volatile("ldmatrix.sync.aligned.m8n8.x4.shared.b16 {%0,%1,%2,%3}, [%4];"
        : "=r"(r0), "=r"(r1), "=r"(r2), "=r"(r3) : "r"(addr));
}
__device__ __forceinline__ void mma16816(float* c, const uint32_t* a, uint32_t b0, uint32_t b1){
    asm volatile("mma.sync.aligned.m16n8k16.row.col.f32.bf16.bf16.f32 "
        "{%0,%1,%2,%3}, {%4,%5,%6,%7}, {%8,%9}, {%0,%1,%2,%3};"
        : "+f"(c[0]), "+f"(c[1]), "+f"(c[2]), "+f"(c[3])
        : "r"(a[0]), "r"(a[1]), "r"(a[2]), "r"(a[3]), "r"(b0), "r"(b1));
}

__device__ __forceinline__ uint32_t pk_bf16(__nv_bfloat16 a, __nv_bfloat16 b){
    uint16_t ua = *reinterpret_cast<uint16_t*>(&a);
    uint16_t ub = *reinterpret_cast<uint16_t*>(&b);
    return (uint32_t)ua | ((uint32_t)ub << 16);
}

// load 128x64 fp32 tile, split into bf16 hi/lo, store SW128-swizzled (8B stores)
__device__ __forceinline__ void load_f32_split(const float* __restrict__ src, int row_stride,
                                               int kofs, char* smem, uint32_t off_hi, uint32_t off_lo,
                                               int tid){
    #pragma unroll
    for (int t=0;t<8;t++){
        int idx = tid + t*256;
        int row = idx >> 4;
        int c4  = idx & 15;
        float4 v = *(const float4*)(src + (size_t)row*row_stride + kofs + c4*4);
        __nv_bfloat16 hx=__float2bfloat16(v.x), hy=__float2bfloat16(v.y);
        __nv_bfloat16 hz=__float2bfloat16(v.z), hw=__float2bfloat16(v.w);
        __nv_bfloat16 lx=__float2bfloat16(v.x-__bfloat162float(hx));
        __nv_bfloat16 ly=__float2bfloat16(v.y-__bfloat162float(hy));
        __nv_bfloat16 lz=__float2bfloat16(v.z-__bfloat162float(hz));
        __nv_bfloat16 lw=__float2bfloat16(v.w-__bfloat162float(hw));
        uint32_t byte = (uint32_t)row*128 + (uint32_t)c4*8;
        uint32_t sw = sw128(byte);
        uint2 ph; ph.x = pk_bf16(hx,hy); ph.y = pk_bf16(hz,hw);
        uint2 pl; pl.x = pk_bf16(lx,ly); pl.y = pk_bf16(lz,lw);
        *(uint2*)(smem + off_hi + sw) = ph;
        *(uint2*)(smem + off_lo + sw) = pl;
    }
}

// copy 128x64 pre-split bf16 tile into SW128-swizzled smem
__device__ __forceinline__ void load_bf16_copy(const __nv_bfloat16* __restrict__ src, int row_stride,
                                               int kofs, char* smem, uint32_t off, int tid){
    #pragma unroll
    for (int t=0;t<8;t++){
        int idx = tid + t*256;
        int row = idx >> 4;
        int c4  = idx & 15;
        uint2 v = *(const uint2*)(src + (size_t)row*row_stride + kofs + c4*4);
        uint32_t byte = (uint32_t)row*128 + (uint32_t)c4*8;
        *(uint2*)(smem + off + sw128(byte)) = v;
    }
}

// ---------------------------------------------------------------------------
// Kernel 1: router
// ---------------------------------------------------------------------------
__global__ __launch_bounds__(256) void router_kernel(
    const float* __restrict__ x, const float* __restrict__ noise,
    const float* __restrict__ rw, const float* __restrict__ rb,
    const float* __restrict__ nw, const float* __restrict__ nb)
{
    int t = blockIdx.x;
    __shared__ float xs[DM];
    __shared__ float sl[NE], sn[NE];
    const float4* xr = (const float4*)(x + (size_t)t * DM);
    for (int i = threadIdx.x; i < DM/4; i += blockDim.x) ((float4*)xs)[i] = xr[i];
    __syncthreads();
    int w = threadIdx.x >> 5, lane = threadIdx.x & 31;
    const float* rwr = rw + w*DM;
    const float* nwr = nw + w*DM;
    float a = 0.f, b = 0.f;
    for (int k = lane; k < DM; k += 32) { float xv = xs[k]; a = fmaf(rwr[k],xv,a); b = fmaf(nwr[k],xv,b); }
    #pragma unroll
    for (int o = 16; o; o >>= 1) { a += __shfl_down_sync(~0u,a,o); b += __shfl_down_sync(~0u,b,o); }
    if (lane == 0) { sl[w] = a + rb[w]; sn[w] = b + nb[w]; }
    __syncthreads();
    if (threadIdx.x == 0) {
        float nz[NE];
        #pragma unroll
        for (int e = 0; e < NE; e++) {
            float z = sn[e];
            float sp = fmaxf(z,0.f) + log1pf(expf(-fabsf(z)));
            nz[e] = sl[e] + noise[t*NE+e]*sp;
        }
        int i0 = 0;
        #pragma unroll
        for (int e = 1; e < NE; e++) if (nz[e] > nz[i0]) i0 = e;
        int i1 = -1;
        #pragma unroll
        for (int e = 0; e < NE; e++) { if (e==i0) continue; if (i1<0 || nz[e]>nz[i1]) i1 = e; }
        float g0 = 1.f/(1.f+expf(nz[i1]-nz[i0]));
        g_topi[t*2+0]=i0; g_topi[t*2+1]=i1;
        g_gate[t*2+0]=g0; g_gate[t*2+1]=1.f-g0;
        g_tok_slot[t*2+0]=-1; g_tok_slot[t*2+1]=-1;
    }
}

// ---------------------------------------------------------------------------
// Kernel 2: capacity assignment (ordered scan) + token->slot inverse map
// ---------------------------------------------------------------------------
__global__ __launch_bounds__(256) void assign_kernel()
{
    int e = blockIdx.x;
    for (int c = threadIdx.x; c < CAP; c += blockDim.x) {
        g_slot_tok[e*CAP+c] = NTOK; g_slot_gate[e*CAP+c] = 0.f;
    }
    __shared__ int base;
    __shared__ int warp_sums[8];
    if (threadIdx.x == 0) base = 0;
    __syncthreads();
    int lane = threadIdx.x & 31, w = threadIdx.x >> 5;
    for (int t0 = 0; t0 < NTOK; t0 += blockDim.x) {
        int t = t0 + threadIdx.x;
        int hit = 0, which = 0; float g = 0.f;
        int i0 = g_topi[t*2], i1 = g_topi[t*2+1];
        if (i0 == e)      { hit = 1; which = 0; g = g_gate[t*2]; }
        else if (i1 == e) { hit = 1; which = 1; g = g_gate[t*2+1]; }
        unsigned ball = __ballot_sync(~0u, hit);
        int wexc = __popc(ball & ((1u<<lane)-1u));
        if (lane == 0) warp_sums[w] = __popc(ball);
        __syncthreads();
        int woff = 0;
        for (int i = 0; i < w; i++) woff += warp_sums[i];
        int pos = base + woff + wexc;
        if (hit && pos < CAP) {
            g_slot_tok[e*CAP+pos] = t;
            g_slot_gate[e*CAP+pos] = g;
            g_tok_slot[t*2+which] = e*CAP+pos;
        }
        __syncthreads();
        if (threadIdx.x == 0) {
            int tot = 0;
            for (int i = 0; i < 8; i++) tot += warp_sums[i];
            base += tot;
        }
        __syncthreads();
    }
}

// ---------------------------------------------------------------------------
// Kernel 3: gather
// ---------------------------------------------------------------------------
__global__ __launch_bounds__(256) void gather_kernel(const float* __restrict__ x)
{
    int c = blockIdx.x, e = blockIdx.y;
    int tok = g_slot_tok[e*CAP+c];
    float4* dst = (float4*)(g_xb + ((size_t)e*CAP + c)*DM);
    if (tok < NTOK) {
        const float4* src = (const float4*)(x + (size_t)tok*DM);
        dst[threadIdx.x] = src[threadIdx.x];
    } else {
        dst[threadIdx.x] = make_float4(0.f,0.f,0.f,0.f);
    }
}

// ---------------------------------------------------------------------------
// Kernel 4: fused stage 1+2 via mma.sync (HMMA fallback; tcgen05 PTX rejected
// by harness's compute_103 target). CTA tile 128x128, 8 warps, warp 64x32,
// 3-term bf16 split accumulate, double-buffered smem (6 tiles/chunk).
// grid (HID/128, CAP/128, NE).
// ---------------------------------------------------------------------------
#define S12_BUF 98304
#define S12_SMEM (2*S12_BUF)

__global__ __launch_bounds__(256,1) void ffn_gemm12(
    const float* __restrict__ xb, const float* __restrict__ w1, const float* __restrict__ w3)
{
    extern __shared__ char smem[];
    const uint32_t sb = smem_u32(smem);
    const int tid = threadIdx.x, wid = tid >> 5, L = tid & 31;
    const int e = blockIdx.z, bm = blockIdx.y*128, bn = blockIdx.x*128;

    const float* A  = xb + ((size_t)e*CAP + bm)*DM;
    const float* B1 = w1 + ((size_t)e*HID + bn)*DM;
    const float* B3 = w3 + ((size_t)e*HID + bn)*DM;

    const int grp = L >> 2, tid4 = L & 3;
    const int m0w = (wid & 1)*64, n0w = (wid >> 1)*32;
    const uint32_t a_row = ((L>>3)&1)*8 + (L&7);
    const uint32_t a_kb  = (L>>4)*16;
    const uint32_t b_row = (L>>4)*8 + (L&7);
    const uint32_t b_kb  = ((L>>3)&1)*16;

    float acc1[4][4][4], acc3[4][4][4];
    #pragma unroll
    for (int i=0;i<4;i++)
        #pragma unroll
        for (int j=0;j<4;j++)
            #pragma unroll
            for (int q=0;q<4;q++){ acc1[i][j][q]=0.f; acc3[i][j][q]=0.f; }

    // preload chunk 0 -> buf 0
    load_f32_split(A , DM, 0, smem, 0,     16384, tid);
    load_f32_split(B1, DM, 0, smem, 32768, 49152, tid);
    load_f32_split(B3, DM, 0, smem, 65536, 81920, tid);
    __syncthreads();

    #pragma unroll 1
    for (int c = 0; c < 16; c++) {
        int b = c & 1;
        if (c + 1 < 16) {
            char* s0 = smem + (b^1)*S12_BUF;
            int kofs = (c+1)*64;
            load_f32_split(A , DM, kofs, s0, 0,     16384, tid);
            load_f32_split(B1, DM, kofs, s0, 32768, 49152, tid);
            load_f32_split(B3, DM, kofs, s0, 65536, 81920, tid);
        }
        uint32_t base = sb + b*S12_BUF;
        #pragma unroll
        for (int kk = 0; kk < 4; kk++) {
            uint32_t f1h[2][4], f1l[2][4], f3h[2][4], f3l[2][4];
            #pragma unroll
            for (int pr = 0; pr < 2; pr++) {
                uint32_t off = sw128((uint32_t)(n0w + pr*16 + b_row)*128u + (uint32_t)kk*32u + b_kb);
                ldsm4(f1h[pr][0],f1h[pr][1],f1h[pr][2],f1h[pr][3], base + 32768 + off);
                ldsm4(f1l[pr][0],f1l[pr][1],f1l[pr][2],f1l[pr][3], base + 49152 + off);
                ldsm4(f3h[pr][0],f3h[pr][1],f3h[pr][2],f3h[pr][3], base + 65536 + off);
                ldsm4(f3l[pr][0],f3l[pr][1],f3l[pr][2],f3l[pr][3], base + 81920 + off);
            }
            #pragma unroll
            for (int ms = 0; ms < 4; ms++) {
                uint32_t aoff = sw128((uint32_t)(m0w + ms*16 + a_row)*128u + (uint32_t)kk*32u + a_kb);
                uint32_t ah[4], al[4];
                ldsm4(ah[0],ah[1],ah[2],ah[3], base + 0     + aoff);
                ldsm4(al[0],al[1],al[2],al[3], base + 16384 + aoff);
                #pragma unroll
                for (int nf = 0; nf < 4; nf++) {
                    int pr = nf >> 1, s = (nf & 1)*2;
                    mma16816(acc1[ms][nf], ah, f1h[pr][s], f1h[pr][s+1]);
                    mma16816(acc1[ms][nf], ah, f1l[pr][s], f1l[pr][s+1]);
                    mma16816(acc1[ms][nf], al, f1h[pr][s], f1h[pr][s+1]);
                    mma16816(acc3[ms][nf], ah, f3h[pr][s], f3h[pr][s+1]);
                    mma16816(acc3[ms][nf], ah, f3l[pr][s], f3l[pr][s+1]);
                    mma16816(acc3[ms][nf], al, f3h[pr][s], f3h[pr][s+1]);
                }
            }
        }
        __syncthreads();
    }

    // epilogue: h = silu(D1)*D3, split to bf16 hi/lo.
    // acc frag: c0,c1 -> (row grp, col 2t4, 2t4+1); c2,c3 -> (row grp+8).
    #pragma unroll
    for (int ms = 0; ms < 4; ms++) {
        #pragma unroll
        for (int nf = 0; nf < 4; nf++) {
            int col = bn + n0w + nf*8 + 2*tid4;
            #pragma unroll
            for (int half = 0; half < 2; half++) {
                int row = bm + m0w + ms*16 + grp + half*8;
                float d1a = acc1[ms][nf][half*2],   d3a = acc3[ms][nf][half*2];
                float d1b = acc1[ms][nf][half*2+1], d3b = acc3[ms][nf][half*2+1];
                float ha = (d1a/(1.f+expf(-d1a)))*d3a;
                float hb = (d1b/(1.f+expf(-d1b)))*d3b;
                __nv_bfloat16 hia = __float2bfloat16(ha), hib = __float2bfloat16(hb);
                __nv_bfloat16 loa = __float2bfloat16(ha-__bfloat162float(hia));
                __nv_bfloat16 lob = __float2bfloat16(hb-__bfloat162float(hib));
                size_t o = ((size_t)e*CAP + row)*HID + col;
                *(uint32_t*)(g_hh + o) = pk_bf16(hia,hib);
                *(uint32_t*)(g_hl + o) = pk_bf16(loa,lob);
            }
        }
    }
}

// ---------------------------------------------------------------------------
// Kernel 5: stage 3 — o = h @ w2^T via mma.sync, gated, store to g_ob
// grid (DM/128, CAP/128, NE), K=HID=2816 (44 chunks), 4 tiles/chunk.
// ---------------------------------------------------------------------------
#define S3_BUF 65536
#define S3_SMEM (2*S3_BUF)

__global__ __launch_bounds__(256,1) void ffn_gemm3(const float* __restrict__ w2)
{
    extern __shared__ char smem[];
    const uint32_t sb = smem_u32(smem);
    const int tid = threadIdx.x, wid = tid >> 5, L = tid & 31;
    const int e = blockIdx.z, bm = blockIdx.y*128, bn = blockIdx.x*128;

    const __nv_bfloat16* Ah = g_hh + ((size_t)e*CAP + bm)*HID;
    const __nv_bfloat16* Al = g_hl + ((size_t)e*CAP + bm)*HID;
    const float* B = w2 + ((size_t)e*DM + bn)*HID;

    const int grp = L >> 2, tid4 = L & 3;
    const int m0w = (wid & 1)*64, n0w = (wid >> 1)*32;
    const uint32_t a_row = ((L>>3)&1)*8 + (L&7);
    const uint32_t a_kb  = (L>>4)*16;
    const uint32_t b_row = (L>>4)*8 + (L&7);
    const uint32_t b_kb  = ((L>>3)&1)*16;

    float acc[4][4][4];
    #pragma unroll
    for (int i=0;i<4;i++)
        #pragma unroll
        for (int j=0;j<4;j++)
            #pragma unroll
            for (int q=0;q<4;q++) acc[i][j][q]=0.f;

    load_bf16_copy(Ah, HID, 0, smem, 0,     tid);
    load_bf16_copy(Al, HID, 0, smem, 16384, tid);
    load_f32_split(B,  HID, 0, smem, 32768, 49152, tid);
    __syncthreads();

    #pragma unroll 1
    for (int c = 0; c < 44; c++) {
        int b = c & 1;
        if (c + 1 < 44) {
            char* s0 = smem + (b^1)*S3_BUF;
            int kofs = (c+1)*64;
            load_bf16_copy(Ah, HID, kofs, s0, 0,     tid);
            load_bf16_copy(Al, HID, kofs, s0, 16384, tid);
            load_f32_split(B,  HID, kofs, s0, 32768, 49152, tid);
        }
        uint32_t base = sb + b*S3_BUF;
        #pragma unroll
        for (int kk = 0; kk < 4; kk++) {
            uint32_t fbh[2][4], fbl[2][4];
            #pragma unroll
            for (int pr = 0; pr < 2; pr++) {
                uint32_t off = sw128((uint32_t)(n0w + pr*16 + b_row)*128u + (uint32_t)kk*32u + b_kb);
                ldsm4(fbh[pr][0],fbh[pr][1],fbh[pr][2],fbh[pr][3], base + 32768 + off);
                ldsm4(fbl[pr][0],fbl[pr][1],fbl[pr][2],fbl[pr][3], base + 49152 + off);
            }
            #pragma unroll
            for (int ms = 0; ms < 4; ms++) {
                uint32_t aoff = sw128((uint32_t)(m0w + ms*16 + a_row)*128u + (uint32_t)kk*32u + a_kb);
                uint32_t ah[4], al[4];
                ldsm4(ah[0],ah[1],ah[2],ah[3], base + 0     + aoff);
                ldsm4(al[0],al[1],al[2],al[3], base + 16384 + aoff);
                #pragma unroll
                for (int nf = 0; nf < 4; nf++) {
                    int pr = nf >> 1, s = (nf & 1)*2;
                    mma16816(acc[ms][nf], ah, fbh[pr][s], fbh[pr][s+1]);
                    mma16816(acc[ms][nf], ah, fbl[pr][s], fbl[pr][s+1]);
                    mma16816(acc[ms][nf], al, fbh[pr][s], fbh[pr][s+1]);
                }
            }
        }
        __syncthreads();
    }

    // epilogue: gated store (float2, cols are even pairs)
    #pragma unroll
    for (int ms = 0; ms < 4; ms++) {
        #pragma unroll
        for (int half = 0; half < 2; half++) {
            int m = bm + m0w + ms*16 + grp + half*8;
            float g = g_slot_gate[e*CAP + m];
            #pragma unroll
            for (int nf = 0; nf < 4; nf++) {
                int col = bn + n0w + nf*8 + 2*tid4;
                float2 v;
                v.x = acc[ms][nf][half*2]   * g;
                v.y = acc[ms][nf][half*2+1] * g;
                *(float2*)(g_ob + ((size_t)e*CAP + m)*DM + col) = v;
            }
        }
    }
}

// ---------------------------------------------------------------------------
// Kernel 6: combine — out[t] = sum of token's (<=2) gated expert rows
// ---------------------------------------------------------------------------
__global__ __launch_bounds__(256) void combine_kernel(float* __restrict__ out)
{
    int t = blockIdx.x, i = threadIdx.x;
    int s0 = g_tok_slot[t*2], s1 = g_tok_slot[t*2+1];
    float4 acc = make_float4(0.f,0.f,0.f,0.f);
    if (s0 >= 0) {
        float4 v = ((const float4*)(g_ob + (size_t)s0*DM))[i];
        acc.x += v.x; acc.y += v.y; acc.z += v.z; acc.w += v.w;
    }
    if (s1 >= 0) {
        float4 v = ((const float4*)(g_ob + (size_t)s1*DM))[i];
        acc.x += v.x; acc.y += v.y; acc.z += v.z; acc.w += v.w;
    }
    ((float4*)(out + (size_t)t*DM))[i] = acc;
}

// ---------------------------------------------------------------------------
// Launch
// ---------------------------------------------------------------------------
extern "C" void kernel_launch(void* const* d_in, const int* in_sizes, int n_in,
                              void* d_out, int out_size)
{
    const float* x   = (const float*)d_in[0];
    const float* nz  = (const float*)d_in[1];
    const float* rw  = (const float*)d_in[2];
    const float* rb  = (const float*)d_in[3];
    const float* nw  = (const float*)d_in[4];
    const float* nb  = (const float*)d_in[5];
    const float* w1  = (const float*)d_in[6];
    const float* w3  = (const float*)d_in[7];
    const float* w2  = (const float*)d_in[8];
    float*       out = (float*)d_out;

    float* xb = nullptr;
    cudaGetSymbolAddress((void**)&xb, g_xb);

    cudaFuncSetAttribute(ffn_gemm12, cudaFuncAttributeMaxDynamicSharedMemorySize, S12_SMEM);
    cudaFuncSetAttribute(ffn_gemm3,  cudaFuncAttributeMaxDynamicSharedMemorySize, S3_SMEM);

    router_kernel<<<NTOK, 256>>>(x, nz, rw, rb, nw, nb);
    assign_kernel<<<NE, 256>>>();
    gather_kernel<<<dim3(CAP, NE), 256>>>(x);
    ffn_gemm12<<<dim3(HID/128, CAP/128, NE), 256, S12_SMEM>>>(xb, w1, w3);
    ffn_gemm3<<<dim3(DM/128, CAP/128, NE), 256, S3_SMEM>>>(w2);
    combine_kernel<<<NTOK, 256>>>(out);
}

// round 11
// speedup vs baseline: 2.1777x; 1.0566x over previous
#include <cuda_runtime.h>
#include <cuda_bf16.h>
#include <cstdint>

#define NTOK 4096
#define DM   1024
#define NE   8
#define CAP  1024
#define HID  2816

// ---------------------------------------------------------------------------
// Static scratch
// ---------------------------------------------------------------------------
__device__ float         g_xb[(size_t)NE*CAP*DM];     // gathered inputs (fp32)
__device__ __nv_bfloat16 g_hh[(size_t)NE*CAP*HID];    // h hi (bf16)
__device__ __nv_bfloat16 g_hl[(size_t)NE*CAP*HID];    // h lo (bf16)
__device__ float         g_ob[(size_t)NE*CAP*DM];     // gated expert outputs
__device__ int   g_slot_tok[NE*CAP];
__device__ float g_slot_gate[NE*CAP];
__device__ int   g_topi[NTOK*2];
__device__ float g_gate[NTOK*2];
__device__ int   g_tok_slot[NTOK*2];                  // token -> expert slot (or -1)

// ---------------------------------------------------------------------------
// Helpers
// ---------------------------------------------------------------------------
__device__ __forceinline__ uint32_t smem_u32(const void* p){
    uint32_t a;
    asm("{ .reg .u64 t; cvta.to.shared.u64 t, %1; cvt.u32.u64 %0, t; }" : "=r"(a) : "l"(p));
    return a;
}
__device__ __forceinline__ uint32_t sw128(uint32_t b){ return b ^ ((b >> 3) & 0x70); }

__device__ __forceinline__ void ldsm4(uint32_t& r0, uint32_t& r1, uint32_t& r2, uint32_t& r3,
                                      uint32_t addr){
    asm volatile("ldmatrix.sync.aligned.m8n8.x4.shared.b16 {%0,%1,%2,%3}, [%4];"
        : "=r"(r0), "=r"(r1), "=r"(r2), "=r"(r3) : "r"(addr));
}
__device__ __forceinline__ void mma16816(float* c, const uint32_t* a, uint32_t b0, uint32_t b1){
    asm volatile("mma.sync.aligned.m16n8k16.row.col.f32.bf16.bf16.f32 "
        "{%0,%1,%2,%3}, {%4,%5,%6,%7}, {%8,%9}, {%0,%1,%2,%3};"
        : "+f"(c[0]), "+f"(c[1]), "+f"(c[2]), "+f"(c[3])
        : "r"(a[0]), "r"(a[1]), "r"(a[2]), "r"(a[3]), "r"(b0), "r"(b1));
}

__device__ __forceinline__ uint32_t pk_bf16(__nv_bfloat16 a, __nv_bfloat16 b){
    uint16_t ua = *reinterpret_cast<uint16_t*>(&a);
    uint16_t ub = *reinterpret_cast<uint16_t*>(&b);
    return (uint32_t)ua | ((uint32_t)ub << 16);
}

// load 128x64 fp32 tile, split into bf16 hi/lo, store SW128-swizzled (8B stores)
template<int NT>
__device__ __forceinline__ void load_f32_split(const float* __restrict__ src, int row_stride,
                                               int kofs, char* smem, uint32_t off_hi, uint32_t off_lo,
                                               int tid){
    #pragma unroll
    for (int t=0;t<2048/NT;t++){
        int idx = tid + t*NT;
        int row = idx >> 4;
        int c4  = idx & 15;
        float4 v = *(const float4*)(src + (size_t)row*row_stride + kofs + c4*4);
        __nv_bfloat16 hx=__float2bfloat16(v.x), hy=__float2bfloat16(v.y);
        __nv_bfloat16 hz=__float2bfloat16(v.z), hw=__float2bfloat16(v.w);
        __nv_bfloat16 lx=__float2bfloat16(v.x-__bfloat162float(hx));
        __nv_bfloat16 ly=__float2bfloat16(v.y-__bfloat162float(hy));
        __nv_bfloat16 lz=__float2bfloat16(v.z-__bfloat162float(hz));
        __nv_bfloat16 lw=__float2bfloat16(v.w-__bfloat162float(hw));
        uint32_t byte = (uint32_t)row*128 + (uint32_t)c4*8;
        uint32_t sw = sw128(byte);
        uint2 ph; ph.x = pk_bf16(hx,hy); ph.y = pk_bf16(hz,hw);
        uint2 pl; pl.x = pk_bf16(lx,ly); pl.y = pk_bf16(lz,lw);
        *(uint2*)(smem + off_hi + sw) = ph;
        *(uint2*)(smem + off_lo + sw) = pl;
    }
}

// copy 128x64 pre-split bf16 tile into SW128-swizzled smem
template<int NT>
__device__ __forceinline__ void load_bf16_copy(const __nv_bfloat16* __restrict__ src, int row_stride,
                                               int kofs, char* smem, uint32_t off, int tid){
    #pragma unroll
    for (int t=0;t<2048/NT;t++){
        int idx = tid + t*NT;
        int row = idx >> 4;
        int c4  = idx & 15;
        uint2 v = *(const uint2*)(src + (size_t)row*row_stride + kofs + c4*4);
        uint32_t byte = (uint32_t)row*128 + (uint32_t)c4*8;
        *(uint2*)(smem + off + sw128(byte)) = v;
    }
}

// ---------------------------------------------------------------------------
// Kernel 1: router
// ---------------------------------------------------------------------------
__global__ __launch_bounds__(256) void router_kernel(
    const float* __restrict__ x, const float* __restrict__ noise,
    const float* __restrict__ rw, const float* __restrict__ rb,
    const float* __restrict__ nw, const float* __restrict__ nb)
{
    int t = blockIdx.x;
    __shared__ float xs[DM];
    __shared__ float sl[NE], sn[NE];
    const float4* xr = (const float4*)(x + (size_t)t * DM);
    for (int i = threadIdx.x; i < DM/4; i += blockDim.x) ((float4*)xs)[i] = xr[i];
    __syncthreads();
    int w = threadIdx.x >> 5, lane = threadIdx.x & 31;
    const float* rwr = rw + w*DM;
    const float* nwr = nw + w*DM;
    float a = 0.f, b = 0.f;
    for (int k = lane; k < DM; k += 32) { float xv = xs[k]; a = fmaf(rwr[k],xv,a); b = fmaf(nwr[k],xv,b); }
    #pragma unroll
    for (int o = 16; o; o >>= 1) { a += __shfl_down_sync(~0u,a,o); b += __shfl_down_sync(~0u,b,o); }
    if (lane == 0) { sl[w] = a + rb[w]; sn[w] = b + nb[w]; }
    __syncthreads();
    if (threadIdx.x == 0) {
        float nz[NE];
        #pragma unroll
        for (int e = 0; e < NE; e++) {
            float z = sn[e];
            float sp = fmaxf(z,0.f) + log1pf(expf(-fabsf(z)));
            nz[e] = sl[e] + noise[t*NE+e]*sp;
        }
        int i0 = 0;
        #pragma unroll
        for (int e = 1; e < NE; e++) if (nz[e] > nz[i0]) i0 = e;
        int i1 = -1;
        #pragma unroll
        for (int e = 0; e < NE; e++) { if (e==i0) continue; if (i1<0 || nz[e]>nz[i1]) i1 = e; }
        float g0 = 1.f/(1.f+expf(nz[i1]-nz[i0]));
        g_topi[t*2+0]=i0; g_topi[t*2+1]=i1;
        g_gate[t*2+0]=g0; g_gate[t*2+1]=1.f-g0;
        g_tok_slot[t*2+0]=-1; g_tok_slot[t*2+1]=-1;
    }
}

// ---------------------------------------------------------------------------
// Kernel 2: capacity assignment (ordered scan) + token->slot inverse map
// ---------------------------------------------------------------------------
__global__ __launch_bounds__(256) void assign_kernel()
{
    int e = blockIdx.x;
    for (int c = threadIdx.x; c < CAP; c += blockDim.x) {
        g_slot_tok[e*CAP+c] = NTOK; g_slot_gate[e*CAP+c] = 0.f;
    }
    __shared__ int base;
    __shared__ int warp_sums[8];
    if (threadIdx.x == 0) base = 0;
    __syncthreads();
    int lane = threadIdx.x & 31, w = threadIdx.x >> 5;
    for (int t0 = 0; t0 < NTOK; t0 += blockDim.x) {
        int t = t0 + threadIdx.x;
        int hit = 0, which = 0; float g = 0.f;
        int i0 = g_topi[t*2], i1 = g_topi[t*2+1];
        if (i0 == e)      { hit = 1; which = 0; g = g_gate[t*2]; }
        else if (i1 == e) { hit = 1; which = 1; g = g_gate[t*2+1]; }
        unsigned ball = __ballot_sync(~0u, hit);
        int wexc = __popc(ball & ((1u<<lane)-1u));
        if (lane == 0) warp_sums[w] = __popc(ball);
        __syncthreads();
        int woff = 0;
        for (int i = 0; i < w; i++) woff += warp_sums[i];
        int pos = base + woff + wexc;
        if (hit && pos < CAP) {
            g_slot_tok[e*CAP+pos] = t;
            g_slot_gate[e*CAP+pos] = g;
            g_tok_slot[t*2+which] = e*CAP+pos;
        }
        __syncthreads();
        if (threadIdx.x == 0) {
            int tot = 0;
            for (int i = 0; i < 8; i++) tot += warp_sums[i];
            base += tot;
        }
        __syncthreads();
    }
}

// ---------------------------------------------------------------------------
// Kernel 3: gather
// ---------------------------------------------------------------------------
__global__ __launch_bounds__(256) void gather_kernel(const float* __restrict__ x)
{
    int c = blockIdx.x, e = blockIdx.y;
    int tok = g_slot_tok[e*CAP+c];
    float4* dst = (float4*)(g_xb + ((size_t)e*CAP + c)*DM);
    if (tok < NTOK) {
        const float4* src = (const float4*)(x + (size_t)tok*DM);
        dst[threadIdx.x] = src[threadIdx.x];
    } else {
        dst[threadIdx.x] = make_float4(0.f,0.f,0.f,0.f);
    }
}

// ---------------------------------------------------------------------------
// Kernel 4: fused stage 1+2 via mma.sync. CTA tile 128x128, 512 threads,
// 16 warps (4m x 4n), warp tile 32x32, 3-term bf16 split, double-buffered.
// grid (HID/128, CAP/128, NE).
// ---------------------------------------------------------------------------
#define S12_BUF 98304
#define S12_SMEM (2*S12_BUF)

__global__ __launch_bounds__(512,1) void ffn_gemm12(
    const float* __restrict__ xb, const float* __restrict__ w1, const float* __restrict__ w3)
{
    extern __shared__ char smem[];
    const uint32_t sb = smem_u32(smem);
    const int tid = threadIdx.x, wid = tid >> 5, L = tid & 31;
    const int e = blockIdx.z, bm = blockIdx.y*128, bn = blockIdx.x*128;

    const float* A  = xb + ((size_t)e*CAP + bm)*DM;
    const float* B1 = w1 + ((size_t)e*HID + bn)*DM;
    const float* B3 = w3 + ((size_t)e*HID + bn)*DM;

    const int grp = L >> 2, tid4 = L & 3;
    const int m0w = (wid & 3)*32, n0w = (wid >> 2)*32;
    const uint32_t a_row = ((L>>3)&1)*8 + (L&7);
    const uint32_t a_kb  = (L>>4)*16;
    const uint32_t b_row = (L>>4)*8 + (L&7);
    const uint32_t b_kb  = ((L>>3)&1)*16;

    float acc1[2][4][4], acc3[2][4][4];
    #pragma unroll
    for (int i=0;i<2;i++)
        #pragma unroll
        for (int j=0;j<4;j++)
            #pragma unroll
            for (int q=0;q<4;q++){ acc1[i][j][q]=0.f; acc3[i][j][q]=0.f; }

    // preload chunk 0 -> buf 0
    load_f32_split<512>(A , DM, 0, smem, 0,     16384, tid);
    load_f32_split<512>(B1, DM, 0, smem, 32768, 49152, tid);
    load_f32_split<512>(B3, DM, 0, smem, 65536, 81920, tid);
    __syncthreads();

    #pragma unroll 1
    for (int c = 0; c < 16; c++) {
        int b = c & 1;
        if (c + 1 < 16) {
            char* s0 = smem + (b^1)*S12_BUF;
            int kofs = (c+1)*64;
            load_f32_split<512>(A , DM, kofs, s0, 0,     16384, tid);
            load_f32_split<512>(B1, DM, kofs, s0, 32768, 49152, tid);
            load_f32_split<512>(B3, DM, kofs, s0, 65536, 81920, tid);
        }
        uint32_t base = sb + b*S12_BUF;
        #pragma unroll
        for (int kk = 0; kk < 4; kk++) {
            // A fragments for both 16-row subtiles (held across pr)
            uint32_t ah[2][4], al[2][4];
            #pragma unroll
            for (int ms = 0; ms < 2; ms++) {
                uint32_t aoff = sw128((uint32_t)(m0w + ms*16 + a_row)*128u + (uint32_t)kk*32u + a_kb);
                ldsm4(ah[ms][0],ah[ms][1],ah[ms][2],ah[ms][3], base + 0     + aoff);
                ldsm4(al[ms][0],al[ms][1],al[ms][2],al[ms][3], base + 16384 + aoff);
            }
            #pragma unroll
            for (int pr = 0; pr < 2; pr++) {
                uint32_t off = sw128((uint32_t)(n0w + pr*16 + b_row)*128u + (uint32_t)kk*32u + b_kb);
                uint32_t f1h[4], f1l[4], f3h[4], f3l[4];
                ldsm4(f1h[0],f1h[1],f1h[2],f1h[3], base + 32768 + off);
                ldsm4(f1l[0],f1l[1],f1l[2],f1l[3], base + 49152 + off);
                ldsm4(f3h[0],f3h[1],f3h[2],f3h[3], base + 65536 + off);
                ldsm4(f3l[0],f3l[1],f3l[2],f3l[3], base + 81920 + off);
                #pragma unroll
                for (int ms = 0; ms < 2; ms++) {
                    #pragma unroll
                    for (int nl = 0; nl < 2; nl++) {
                        int nf = pr*2 + nl, s = nl*2;
                        mma16816(acc1[ms][nf], ah[ms], f1h[s], f1h[s+1]);
                        mma16816(acc1[ms][nf], ah[ms], f1l[s], f1l[s+1]);
                        mma16816(acc1[ms][nf], al[ms], f1h[s], f1h[s+1]);
                        mma16816(acc3[ms][nf], ah[ms], f3h[s], f3h[s+1]);
                        mma16816(acc3[ms][nf], ah[ms], f3l[s], f3l[s+1]);
                        mma16816(acc3[ms][nf], al[ms], f3h[s], f3h[s+1]);
                    }
                }
            }
        }
        __syncthreads();
    }

    // epilogue: h = silu(D1)*D3, split to bf16 hi/lo.
    #pragma unroll
    for (int ms = 0; ms < 2; ms++) {
        #pragma unroll
        for (int nf = 0; nf < 4; nf++) {
            int col = bn + n0w + nf*8 + 2*tid4;
            #pragma unroll
            for (int half = 0; half < 2; half++) {
                int row = bm + m0w + ms*16 + grp + half*8;
                float d1a = acc1[ms][nf][half*2],   d3a = acc3[ms][nf][half*2];
                float d1b = acc1[ms][nf][half*2+1], d3b = acc3[ms][nf][half*2+1];
                float ha = (d1a/(1.f+expf(-d1a)))*d3a;
                float hb = (d1b/(1.f+expf(-d1b)))*d3b;
                __nv_bfloat16 hia = __float2bfloat16(ha), hib = __float2bfloat16(hb);
                __nv_bfloat16 loa = __float2bfloat16(ha-__bfloat162float(hia));
                __nv_bfloat16 lob = __float2bfloat16(hb-__bfloat162float(hib));
                size_t o = ((size_t)e*CAP + row)*HID + col;
                *(uint32_t*)(g_hh + o) = pk_bf16(hia,hib);
                *(uint32_t*)(g_hl + o) = pk_bf16(loa,lob);
            }
        }
    }
}

// ---------------------------------------------------------------------------
// Kernel 5: stage 3 — o = h @ w2^T via mma.sync, gated. 512 threads,
// warp tile 32x32. grid (DM/128, CAP/128, NE), K=HID (44 chunks).
// ---------------------------------------------------------------------------
#define S3_BUF 65536
#define S3_SMEM (2*S3_BUF)

__global__ __launch_bounds__(512,1) void ffn_gemm3(const float* __restrict__ w2)
{
    extern __shared__ char smem[];
    const uint32_t sb = smem_u32(smem);
    const int tid = threadIdx.x, wid = tid >> 5, L = tid & 31;
    const int e = blockIdx.z, bm = blockIdx.y*128, bn = blockIdx.x*128;

    const __nv_bfloat16* Ah = g_hh + ((size_t)e*CAP + bm)*HID;
    const __nv_bfloat16* Al = g_hl + ((size_t)e*CAP + bm)*HID;
    const float* B = w2 + ((size_t)e*DM + bn)*HID;

    const int grp = L >> 2, tid4 = L & 3;
    const int m0w = (wid & 3)*32, n0w = (wid >> 2)*32;
    const uint32_t a_row = ((L>>3)&1)*8 + (L&7);
    const uint32_t a_kb  = (L>>4)*16;
    const uint32_t b_row = (L>>4)*8 + (L&7);
    const uint32_t b_kb  = ((L>>3)&1)*16;

    float acc[2][4][4];
    #pragma unroll
    for (int i=0;i<2;i++)
        #pragma unroll
        for (int j=0;j<4;j++)
            #pragma unroll
            for (int q=0;q<4;q++) acc[i][j][q]=0.f;

    load_bf16_copy<512>(Ah, HID, 0, smem, 0,     tid);
    load_bf16_copy<512>(Al, HID, 0, smem, 16384, tid);
    load_f32_split<512>(B,  HID, 0, smem, 32768, 49152, tid);
    __syncthreads();

    #pragma unroll 1
    for (int c = 0; c < 44; c++) {
        int b = c & 1;
        if (c + 1 < 44) {
            char* s0 = smem + (b^1)*S3_BUF;
            int kofs = (c+1)*64;
            load_bf16_copy<512>(Ah, HID, kofs, s0, 0,     tid);
            load_bf16_copy<512>(Al, HID, kofs, s0, 16384, tid);
            load_f32_split<512>(B,  HID, kofs, s0, 32768, 49152, tid);
        }
        uint32_t base = sb + b*S3_BUF;
        #pragma unroll
        for (int kk = 0; kk < 4; kk++) {
            uint32_t ah[2][4], al[2][4];
            #pragma unroll
            for (int ms = 0; ms < 2; ms++) {
                uint32_t aoff = sw128((uint32_t)(m0w + ms*16 + a_row)*128u + (uint32_t)kk*32u + a_kb);
                ldsm4(ah[ms][0],ah[ms][1],ah[ms][2],ah[ms][3], base + 0     + aoff);
                ldsm4(al[ms][0],al[ms][1],al[ms][2],al[ms][3], base + 16384 + aoff);
            }
            #pragma unroll
            for (int pr = 0; pr < 2; pr++) {
                uint32_t off = sw128((uint32_t)(n0w + pr*16 + b_row)*128u + (uint32_t)kk*32u + b_kb);
                uint32_t fbh[4], fbl[4];
                ldsm4(fbh[0],fbh[1],fbh[2],fbh[3], base + 32768 + off);
                ldsm4(fbl[0],fbl[1],fbl[2],fbl[3], base + 49152 + off);
                #pragma unroll
                for (int ms = 0; ms < 2; ms++) {
                    #pragma unroll
                    for (int nl = 0; nl < 2; nl++) {
                        int nf = pr*2 + nl, s = nl*2;
                        mma16816(acc[ms][nf], ah[ms], fbh[s], fbh[s+1]);
                        mma16816(acc[ms][nf], ah[ms], fbl[s], fbl[s+1]);
                        mma16816(acc[ms][nf], al[ms], fbh[s], fbh[s+1]);
                    }
                }
            }
        }
        __syncthreads();
    }

    // epilogue: gated store (float2, col pairs)
    #pragma unroll
    for (int ms = 0; ms < 2; ms++) {
        #pragma unroll
        for (int half = 0; half < 2; half++) {
            int m = bm + m0w + ms*16 + grp + half*8;
            float g = g_slot_gate[e*CAP + m];
            #pragma unroll
            for (int nf = 0; nf < 4; nf++) {
                int col = bn + n0w + nf*8 + 2*tid4;
                float2 v;
                v.x = acc[ms][nf][half*2]   * g;
                v.y = acc[ms][nf][half*2+1] * g;
                *(float2*)(g_ob + ((size_t)e*CAP + m)*DM + col) = v;
            }
        }
    }
}

// ---------------------------------------------------------------------------
// Kernel 6: combine — out[t] = sum of token's (<=2) gated expert rows
// ---------------------------------------------------------------------------
__global__ __launch_bounds__(256) void combine_kernel(float* __restrict__ out)
{
    int t = blockIdx.x, i = threadIdx.x;
    int s0 = g_tok_slot[t*2], s1 = g_tok_slot[t*2+1];
    float4 acc = make_float4(0.f,0.f,0.f,0.f);
    if (s0 >= 0) {
        float4 v = ((const float4*)(g_ob + (size_t)s0*DM))[i];
        acc.x += v.x; acc.y += v.y; acc.z += v.z; acc.w += v.w;
    }
    if (s1 >= 0) {
        float4 v = ((const float4*)(g_ob + (size_t)s1*DM))[i];
        acc.x += v.x; acc.y += v.y; acc.z += v.z; acc.w += v.w;
    }
    ((float4*)(out + (size_t)t*DM))[i] = acc;
}

// ---------------------------------------------------------------------------
// Launch
// ---------------------------------------------------------------------------
extern "C" void kernel_launch(void* const* d_in, const int* in_sizes, int n_in,
                              void* d_out, int out_size)
{
    const float* x   = (const float*)d_in[0];
    const float* nz  = (const float*)d_in[1];
    const float* rw  = (const float*)d_in[2];
    const float* rb  = (const float*)d_in[3];
    const float* nw  = (const float*)d_in[4];
    const float* nb  = (const float*)d_in[5];
    const float* w1  = (const float*)d_in[6];
    const float* w3  = (const float*)d_in[7];
    const float* w2  = (const float*)d_in[8];
    float*       out = (float*)d_out;

    float* xb = nullptr;
    cudaGetSymbolAddress((void**)&xb, g_xb);

    cudaFuncSetAttribute(ffn_gemm12, cudaFuncAttributeMaxDynamicSharedMemorySize, S12_SMEM);
    cudaFuncSetAttribute(ffn_gemm3,  cudaFuncAttributeMaxDynamicSharedMemorySize, S3_SMEM);

    router_kernel<<<NTOK, 256>>>(x, nz, rw, rb, nw, nb);
    assign_kernel<<<NE, 256>>>();
    gather_kernel<<<dim3(CAP, NE), 256>>>(x);
    ffn_gemm12<<<dim3(HID/128, CAP/128, NE), 512, S12_SMEM>>>(xb, w1, w3);
    ffn_gemm3<<<dim3(DM/128, CAP/128, NE), 512, S3_SMEM>>>(w2);
    combine_kernel<<<NTOK, 256>>>(out);
}